// round 3
// baseline (speedup 1.0000x reference)
#include <cuda_runtime.h>
#include <math.h>
#include <float.h>

#define MAXBT 1024
__device__ float g_loss_part[MAXBT];
__device__ float g_lossc_part[MAXBT];
__device__ unsigned int g_count;

typedef unsigned long long u64;

__device__ __forceinline__ u64 pk2(float lo, float hi) {
    u64 r; asm("mov.b64 %0, {%1,%2};" : "=l"(r) : "f"(lo), "f"(hi)); return r;
}
__device__ __forceinline__ void upk2(float& lo, float& hi, u64 v) {
    asm("mov.b64 {%0,%1}, %2;" : "=f"(lo), "=f"(hi) : "l"(v));
}
__device__ __forceinline__ u64 ffma2(u64 a, u64 b, u64 c) {
    u64 d; asm("fma.rn.f32x2 %0, %1, %2, %3;" : "=l"(d) : "l"(a), "l"(b), "l"(c)); return d;
}
__device__ __forceinline__ u64 addf2(u64 a, u64 b) {
    u64 d; asm("add.rn.f32x2 %0, %1, %2;" : "=l"(d) : "l"(a), "l"(b)); return d;
}

__device__ __forceinline__ float sl1(float a, float b) {
    float d = fabsf(a - b);
    return d < 1.0f ? 0.5f * d * d : d - 0.5f;
}

__device__ __forceinline__ float blockReduceSum(float v, float* red) {
    #pragma unroll
    for (int o = 16; o > 0; o >>= 1)
        v += __shfl_down_sync(0xffffffffu, v, o);
    int lane = threadIdx.x & 31;
    int wid  = threadIdx.x >> 5;
    __syncthreads();
    if (lane == 0) red[wid] = v;
    __syncthreads();
    if (wid == 0) {
        v = (lane < (int)(blockDim.x >> 5)) ? red[lane] : 0.0f;
        #pragma unroll
        for (int o = 16; o > 0; o >>= 1)
            v += __shfl_down_sync(0xffffffffu, v, o);
    }
    return v;
}

// One CTA per (b,t). 1024 threads, one pred point each. Targets staged in smem
// as paired layout for f32x2 math:
//   sA[m2] = (-2tx[2m2], -2tx[2m2+1], -2ty[2m2], -2ty[2m2+1])
//   sB[m2] = (-2tz[2m2], -2tz[2m2+1],  tn[2m2],  tn[2m2+1])
// Argmin via packed key: key = bits(dist^2) with low 10 mantissa bits replaced
// by the target index; single IMNMX per candidate, no predicates.
__global__ __launch_bounds__(1024, 1)
void nn_loss_kernel(const float* __restrict__ X,
                    const float* __restrict__ T,
                    const float* __restrict__ W,
                    float* __restrict__ out,
                    int N, int BT, int B)
{
    extern __shared__ float4 smem4[];
    float4* sA = smem4;            // N/2 float4
    float4* sB = smem4 + (N >> 1); // N/2 float4
    __shared__ float red[32];
    __shared__ int isLast;

    const int bt  = blockIdx.x;
    const int tid = threadIdx.x;
    const float* Xb = X + (size_t)bt * N * 3;
    const float* Tb = T + (size_t)bt * N * 3;

    // Stage target tid (prescaled by -2, plus squared norm).
    float t0 = Tb[tid * 3 + 0];
    float t1 = Tb[tid * 3 + 1];
    float t2 = Tb[tid * 3 + 2];
    float tn = fmaf(t0, t0, fmaf(t1, t1, t2 * t2));
    {
        int m2 = tid >> 1, par = tid & 1;
        float* A  = (float*)&sA[m2];
        float* Bp = (float*)&sB[m2];
        A[par]      = -2.0f * t0;
        A[2 + par]  = -2.0f * t1;
        Bp[par]     = -2.0f * t2;
        Bp[2 + par] = tn;
    }

    float x0 = Xb[tid * 3 + 0];
    float x1 = Xb[tid * 3 + 1];
    float x2 = Xb[tid * 3 + 2];
    float xn = fmaf(x0, x0, fmaf(x1, x1, x2 * x2));

    __syncthreads();

    u64 xx0 = pk2(x0, x0), xx1 = pk2(x1, x1), xx2 = pk2(x2, x2);
    u64 xnxn = pk2(xn, xn);
    const ulonglong2* pA = (const ulonglong2*)sA;
    const ulonglong2* pB = (const ulonglong2*)sB;

    // dist^2 = xn + tn - 2 x.t  >= 0 (up to rounding), so float bits order
    // like uints. Low 10 mantissa bits carry the index (2^-13 relative
    // truncation -- far below NN distance gaps).
    unsigned int best0 = 0xFFFFFFFFu, best1 = 0xFFFFFFFFu;
    unsigned int i0 = 0u, i1 = 1u;
    const int half = N >> 1;
    #pragma unroll 8
    for (int m2 = 0; m2 < half; ++m2) {
        ulonglong2 a = pA[m2];   // (tx0,tx1), (ty0,ty1)  [prescaled by -2]
        ulonglong2 b = pB[m2];   // (tz0,tz1), (tn0,tn1)
        u64 dp = ffma2(xx0, a.x, ffma2(xx1, a.y, ffma2(xx2, b.x, b.y)));
        dp = addf2(dp, xnxn);    // true squared distance (non-negative)
        float d0, d1;
        upk2(d0, d1, dp);
        unsigned int k0 = (__float_as_uint(d0) & 0xFFFFFC00u) | i0;
        unsigned int k1 = (__float_as_uint(d1) & 0xFFFFFC00u) | i1;
        best0 = min(best0, k0);
        best1 = min(best1, k1);
        i0 += 2u; i1 += 2u;
    }
    unsigned int best = min(best0, best1);
    int bidx = (int)(best & 1023u);

    // Recover winning target coords (undo -2 prescale).
    int bm2 = bidx >> 1, bp = bidx & 1;
    const float* Af = (const float*)&sA[bm2];
    const float* Bf = (const float*)&sB[bm2];
    float bt0 = -0.5f * Af[bp];
    float bt1 = -0.5f * Af[2 + bp];
    float bt2 = -0.5f * Bf[bp];

    float s = sl1(x0, bt0) + sl1(x1, bt1) + sl1(x2, bt2);

    float S   = blockReduceSum(s,  red);
    float sx0 = blockReduceSum(x0, red);
    float sx1 = blockReduceSum(x1, red);
    float sx2 = blockReduceSum(x2, red);
    float st0 = blockReduceSum(t0, red);
    float st1 = blockReduceSum(t1, red);
    float st2 = blockReduceSum(t2, red);

    if (tid == 0) {
        g_loss_part[bt] = W[bt] * S;
        float inv = 1.0f / (float)N;
        g_lossc_part[bt] = sl1(sx0 * inv, st0 * inv)
                         + sl1(sx1 * inv, st1 * inv)
                         + sl1(sx2 * inv, st2 * inv);
        __threadfence();
        unsigned int prev = atomicAdd(&g_count, 1u);
        isLast = (prev == (unsigned int)(gridDim.x - 1)) ? 1 : 0;
    }
    __syncthreads();

    // Last CTA finalizes with warp 0 (deterministic order).
    if (isLast && tid < 32) {
        __threadfence();
        float s1 = 0.0f, s2 = 0.0f;
        for (int i = tid; i < BT; i += 32) {
            s1 += g_loss_part[i];
            s2 += g_lossc_part[i];
        }
        #pragma unroll
        for (int o = 16; o > 0; o >>= 1) {
            s1 += __shfl_down_sync(0xffffffffu, s1, o);
            s2 += __shfl_down_sync(0xffffffffu, s2, o);
        }
        if (tid == 0) {
            out[0] = s1 / (3.0f * (float)N * (float)B);
            out[1] = s2 / ((float)B * 3.0f);
            g_count = 0;   // reset for next graph replay
        }
    }
}

extern "C" void kernel_launch(void* const* d_in, const int* in_sizes, int n_in,
                              void* d_out, int out_size)
{
    const float* X = (const float*)d_in[0];   // [B,T,N,3]
    const float* T = (const float*)d_in[1];   // [B,T,N,3]
    const float* W = (const float*)d_in[2];   // [B,T]
    float* out = (float*)d_out;

    const int BT = in_sizes[2];               // 112
    const int N  = in_sizes[0] / (BT * 3);    // 1024
    const int B  = 4;

    size_t smem = (size_t)N * sizeof(float4); // 16 KB
    nn_loss_kernel<<<BT, N, smem>>>(X, T, W, out, N, BT, B);
}

// round 4
// speedup vs baseline: 1.0376x; 1.0376x over previous
#include <cuda_runtime.h>
#include <math.h>
#include <float.h>

#define MAXBT 1024
__device__ float g_loss_part[MAXBT];
__device__ float g_lossc_part[MAXBT];
__device__ unsigned int g_count;

typedef unsigned long long u64;

__device__ __forceinline__ u64 pk2(float lo, float hi) {
    u64 r; asm("mov.b64 %0, {%1,%2};" : "=l"(r) : "f"(lo), "f"(hi)); return r;
}
__device__ __forceinline__ void upk2(float& lo, float& hi, u64 v) {
    asm("mov.b64 {%0,%1}, %2;" : "=f"(lo), "=f"(hi) : "l"(v));
}
__device__ __forceinline__ u64 ffma2(u64 a, u64 b, u64 c) {
    u64 d; asm("fma.rn.f32x2 %0, %1, %2, %3;" : "=l"(d) : "l"(a), "l"(b), "l"(c)); return d;
}

__device__ __forceinline__ float sl1(float a, float b) {
    float d = fabsf(a - b);
    return d < 1.0f ? 0.5f * d * d : d - 0.5f;
}

__device__ __forceinline__ float blockReduceSum(float v, float* red) {
    #pragma unroll
    for (int o = 16; o > 0; o >>= 1)
        v += __shfl_down_sync(0xffffffffu, v, o);
    int lane = threadIdx.x & 31;
    int wid  = threadIdx.x >> 5;
    __syncthreads();
    if (lane == 0) red[wid] = v;
    __syncthreads();
    if (wid == 0) {
        v = (lane < (int)(blockDim.x >> 5)) ? red[lane] : 0.0f;
        #pragma unroll
        for (int o = 16; o > 0; o >>= 1)
            v += __shfl_down_sync(0xffffffffu, v, o);
    }
    return v;
}

// One CTA per (b,t). 1024 threads, one pred point each. Targets staged in smem
// as paired layout for f32x2 math:
//   sA[m2] = (-2tx[2m2], -2tx[2m2+1], -2ty[2m2], -2ty[2m2+1])
//   sB[m2] = (-2tz[2m2], -2tz[2m2+1],  tn[2m2],  tn[2m2+1])
// Argmin: 4 targets/iter with 4 INDEPENDENT (best,step) chains sharing one
// induction variable; chain id recovered at merge time.
__global__ __launch_bounds__(1024, 1)
void nn_loss_kernel(const float* __restrict__ X,
                    const float* __restrict__ T,
                    const float* __restrict__ W,
                    float* __restrict__ out,
                    int N, int BT, int B)
{
    extern __shared__ float4 smem4[];
    float4* sA = smem4;            // N/2 float4
    float4* sB = smem4 + (N >> 1); // N/2 float4
    __shared__ float red[32];
    __shared__ int isLast;

    const int bt  = blockIdx.x;
    const int tid = threadIdx.x;
    const float* Xb = X + (size_t)bt * N * 3;
    const float* Tb = T + (size_t)bt * N * 3;

    // Stage target tid (prescaled by -2, plus squared norm).
    float t0 = Tb[tid * 3 + 0];
    float t1 = Tb[tid * 3 + 1];
    float t2 = Tb[tid * 3 + 2];
    float tn = fmaf(t0, t0, fmaf(t1, t1, t2 * t2));
    {
        int m2 = tid >> 1, par = tid & 1;
        float* A  = (float*)&sA[m2];
        float* Bp = (float*)&sB[m2];
        A[par]      = -2.0f * t0;
        A[2 + par]  = -2.0f * t1;
        Bp[par]     = -2.0f * t2;
        Bp[2 + par] = tn;
    }

    float x0 = Xb[tid * 3 + 0];
    float x1 = Xb[tid * 3 + 1];
    float x2 = Xb[tid * 3 + 2];

    __syncthreads();

    u64 xx0 = pk2(x0, x0), xx1 = pk2(x1, x1), xx2 = pk2(x2, x2);
    const ulonglong2* pA = (const ulonglong2*)sA;
    const ulonglong2* pB = (const ulonglong2*)sB;

    // key = tn - 2 x.t  (monotone in true sq-dist; |x|^2 const per thread).
    // 4 independent chains: chain k covers targets with (index mod 4) == k.
    // Each chain records the step number m4 at which its best occurred.
    float b0 = FLT_MAX, b1 = FLT_MAX, b2 = FLT_MAX, b3 = FLT_MAX;
    int   s0 = 0, s1 = 0, s2 = 0, s3 = 0;

    const int quarter = N >> 2;
    #pragma unroll 4
    for (int m4 = 0; m4 < quarter; ++m4) {
        int m2 = m4 << 1;
        ulonglong2 a0 = pA[m2];
        ulonglong2 c0 = pB[m2];
        ulonglong2 a1 = pA[m2 + 1];
        ulonglong2 c1 = pB[m2 + 1];
        u64 dp0 = ffma2(xx0, a0.x, ffma2(xx1, a0.y, ffma2(xx2, c0.x, c0.y)));
        u64 dp1 = ffma2(xx0, a1.x, ffma2(xx1, a1.y, ffma2(xx2, c1.x, c1.y)));
        float d0, d1, d2, d3;
        upk2(d0, d1, dp0);
        upk2(d2, d3, dp1);
        // Independent updates: strict '<' keeps first (lowest-index) min.
        s0 = (d0 < b0) ? m4 : s0;  b0 = fminf(b0, d0);
        s1 = (d1 < b1) ? m4 : s1;  b1 = fminf(b1, d1);
        s2 = (d2 < b2) ? m4 : s2;  b2 = fminf(b2, d2);
        s3 = (d3 < b3) ? m4 : s3;  b3 = fminf(b3, d3);
    }

    // Merge 4 chains; tie-break = lowest global index (chain order 0..3).
    float best = b0; int bidx = (s0 << 2);
    { int i = (s1 << 2) | 1; if (b1 < best || (b1 == best && i < bidx)) { best = b1; bidx = i; } }
    { int i = (s2 << 2) | 2; if (b2 < best || (b2 == best && i < bidx)) { best = b2; bidx = i; } }
    { int i = (s3 << 2) | 3; if (b3 < best || (b3 == best && i < bidx)) { best = b3; bidx = i; } }

    // Recover winning target coords (undo -2 prescale).
    int bm2 = bidx >> 1, bp = bidx & 1;
    const float* Af = (const float*)&sA[bm2];
    const float* Bf = (const float*)&sB[bm2];
    float bt0 = -0.5f * Af[bp];
    float bt1 = -0.5f * Af[2 + bp];
    float bt2 = -0.5f * Bf[bp];

    float s = sl1(x0, bt0) + sl1(x1, bt1) + sl1(x2, bt2);

    float S   = blockReduceSum(s,  red);
    float sx0 = blockReduceSum(x0, red);
    float sx1 = blockReduceSum(x1, red);
    float sx2 = blockReduceSum(x2, red);
    float st0 = blockReduceSum(t0, red);
    float st1 = blockReduceSum(t1, red);
    float st2 = blockReduceSum(t2, red);

    if (tid == 0) {
        g_loss_part[bt] = W[bt] * S;
        float inv = 1.0f / (float)N;
        g_lossc_part[bt] = sl1(sx0 * inv, st0 * inv)
                         + sl1(sx1 * inv, st1 * inv)
                         + sl1(sx2 * inv, st2 * inv);
        __threadfence();
        unsigned int prev = atomicAdd(&g_count, 1u);
        isLast = (prev == (unsigned int)(gridDim.x - 1)) ? 1 : 0;
    }
    __syncthreads();

    // Last CTA finalizes with warp 0 (deterministic order).
    if (isLast && tid < 32) {
        __threadfence();
        float v1 = 0.0f, v2 = 0.0f;
        for (int i = tid; i < BT; i += 32) {
            v1 += g_loss_part[i];
            v2 += g_lossc_part[i];
        }
        #pragma unroll
        for (int o = 16; o > 0; o >>= 1) {
            v1 += __shfl_down_sync(0xffffffffu, v1, o);
            v2 += __shfl_down_sync(0xffffffffu, v2, o);
        }
        if (tid == 0) {
            out[0] = v1 / (3.0f * (float)N * (float)B);
            out[1] = v2 / ((float)B * 3.0f);
            g_count = 0;   // reset for next graph replay
        }
    }
}

extern "C" void kernel_launch(void* const* d_in, const int* in_sizes, int n_in,
                              void* d_out, int out_size)
{
    const float* X = (const float*)d_in[0];   // [B,T,N,3]
    const float* T = (const float*)d_in[1];   // [B,T,N,3]
    const float* W = (const float*)d_in[2];   // [B,T]
    float* out = (float*)d_out;

    const int BT = in_sizes[2];               // 112
    const int N  = in_sizes[0] / (BT * 3);    // 1024
    const int B  = 4;

    size_t smem = (size_t)N * sizeof(float4); // 16 KB
    nn_loss_kernel<<<BT, N, smem>>>(X, T, W, out, N, BT, B);
}

// round 5
// speedup vs baseline: 1.2206x; 1.1763x over previous
#include <cuda_runtime.h>
#include <math.h>
#include <float.h>

#define MAXBT 1024
__device__ float g_loss_part[MAXBT];
__device__ float g_lossc_part[MAXBT];
__device__ unsigned int g_count;

typedef unsigned long long u64;

__device__ __forceinline__ u64 pk2(float lo, float hi) {
    u64 r; asm("mov.b64 %0, {%1,%2};" : "=l"(r) : "f"(lo), "f"(hi)); return r;
}
__device__ __forceinline__ void upk2(float& lo, float& hi, u64 v) {
    asm("mov.b64 {%0,%1}, %2;" : "=f"(lo), "=f"(hi) : "l"(v));
}
__device__ __forceinline__ u64 ffma2(u64 a, u64 b, u64 c) {
    u64 d; asm("fma.rn.f32x2 %0, %1, %2, %3;" : "=l"(d) : "l"(a), "l"(b), "l"(c)); return d;
}
__device__ __forceinline__ u64 addf2(u64 a, u64 b) {
    u64 d; asm("add.rn.f32x2 %0, %1, %2;" : "=l"(d) : "l"(a), "l"(b)); return d;
}

__device__ __forceinline__ float sl1(float a, float b) {
    float d = fabsf(a - b);
    return d < 1.0f ? 0.5f * d * d : d - 0.5f;
}

__device__ __forceinline__ float blockReduceSum(float v, float* red) {
    #pragma unroll
    for (int o = 16; o > 0; o >>= 1)
        v += __shfl_down_sync(0xffffffffu, v, o);
    int lane = threadIdx.x & 31;
    int wid  = threadIdx.x >> 5;
    __syncthreads();
    if (lane == 0) red[wid] = v;
    __syncthreads();
    if (wid == 0) {
        v = (lane < (int)(blockDim.x >> 5)) ? red[lane] : 0.0f;
        #pragma unroll
        for (int o = 16; o > 0; o >>= 1)
            v += __shfl_down_sync(0xffffffffu, v, o);
    }
    return v;
}

// One CTA per (b,t). 512 threads; each thread owns TWO pred points (tid and
// tid+512) so every staged target pair feeds 4 distance evaluations.
// Targets in smem, paired layout for f32x2 math:
//   sA[m2] = (-2tx[2m2], -2tx[2m2+1], -2ty[2m2], -2ty[2m2+1])
//   sB[m2] = (-2tz[2m2], -2tz[2m2+1],  tn[2m2],  tn[2m2+1])
// Argmin: packed keys. key = bits(dist^2) with low 9 mantissa bits = m2.
// dist^2 >= 0 so float bits order as uints; 4 independent IMNMX.U32 chains
// (pred x parity); parity implicit in chain id, m2 embedded in key.
__global__ __launch_bounds__(512, 1)
void nn_loss_kernel(const float* __restrict__ X,
                    const float* __restrict__ T,
                    const float* __restrict__ W,
                    float* __restrict__ out,
                    int N, int BT, int B)
{
    extern __shared__ float4 smem4[];
    float4* sA = smem4;            // N/2 float4
    float4* sB = smem4 + (N >> 1); // N/2 float4
    __shared__ float red[32];
    __shared__ int isLast;

    const int bt   = blockIdx.x;
    const int tid  = threadIdx.x;
    const int half = N >> 1;       // 512
    const float* Xb = X + (size_t)bt * N * 3;
    const float* Tb = T + (size_t)bt * N * 3;

    // Stage two targets: indices tid and tid+half.
    float ta0, ta1, ta2, tb0, tb1, tb2;
    {
        int i0 = tid, i1 = tid + half;
        ta0 = Tb[i0 * 3 + 0]; ta1 = Tb[i0 * 3 + 1]; ta2 = Tb[i0 * 3 + 2];
        tb0 = Tb[i1 * 3 + 0]; tb1 = Tb[i1 * 3 + 1]; tb2 = Tb[i1 * 3 + 2];
        float na = fmaf(ta0, ta0, fmaf(ta1, ta1, ta2 * ta2));
        float nb = fmaf(tb0, tb0, fmaf(tb1, tb1, tb2 * tb2));
        int m2a = i0 >> 1, pa = i0 & 1;
        int m2b = i1 >> 1, pb = i1 & 1;
        float* A; float* Bp;
        A = (float*)&sA[m2a]; Bp = (float*)&sB[m2a];
        A[pa] = -2.0f * ta0; A[2 + pa] = -2.0f * ta1;
        Bp[pa] = -2.0f * ta2; Bp[2 + pa] = na;
        A = (float*)&sA[m2b]; Bp = (float*)&sB[m2b];
        A[pb] = -2.0f * tb0; A[2 + pb] = -2.0f * tb1;
        Bp[pb] = -2.0f * tb2; Bp[2 + pb] = nb;
    }

    // Two pred points: indices tid and tid+half.
    float xa0 = Xb[tid * 3 + 0], xa1 = Xb[tid * 3 + 1], xa2 = Xb[tid * 3 + 2];
    float xb0 = Xb[(tid + half) * 3 + 0], xb1 = Xb[(tid + half) * 3 + 1], xb2 = Xb[(tid + half) * 3 + 2];
    float xna = fmaf(xa0, xa0, fmaf(xa1, xa1, xa2 * xa2));
    float xnb = fmaf(xb0, xb0, fmaf(xb1, xb1, xb2 * xb2));

    __syncthreads();

    u64 A0 = pk2(xa0, xa0), A1 = pk2(xa1, xa1), A2 = pk2(xa2, xa2);
    u64 B0 = pk2(xb0, xb0), B1 = pk2(xb1, xb1), B2 = pk2(xb2, xb2);
    u64 NA = pk2(xna, xna), NB = pk2(xnb, xnb);
    const ulonglong2* pA = (const ulonglong2*)sA;
    const ulonglong2* pB = (const ulonglong2*)sB;

    const unsigned MASK = 0xFFFFFE00u;   // keep 14 mantissa bits, low 9 = m2
    unsigned bA0 = 0xFFFFFFFFu, bA1 = 0xFFFFFFFFu;   // pred A: even/odd chains
    unsigned bB0 = 0xFFFFFFFFu, bB1 = 0xFFFFFFFFu;   // pred B

    #pragma unroll 8
    for (int m2 = 0; m2 < half; ++m2) {
        ulonglong2 a = pA[m2];   // (tx_e,tx_o),(ty_e,ty_o) prescaled by -2
        ulonglong2 b = pB[m2];   // (tz_e,tz_o),(tn_e,tn_o)
        u64 dA = addf2(ffma2(A0, a.x, ffma2(A1, a.y, ffma2(A2, b.x, b.y))), NA);
        u64 dB = addf2(ffma2(B0, a.x, ffma2(B1, a.y, ffma2(B2, b.x, b.y))), NB);
        float dA0, dA1, dB0, dB1;
        upk2(dA0, dA1, dA);
        upk2(dB0, dB1, dB);
        unsigned mu = (unsigned)m2;
        bA0 = min(bA0, (__float_as_uint(dA0) & MASK) | mu);
        bA1 = min(bA1, (__float_as_uint(dA1) & MASK) | mu);
        bB0 = min(bB0, (__float_as_uint(dB0) & MASK) | mu);
        bB1 = min(bB1, (__float_as_uint(dB1) & MASK) | mu);
    }

    // Merge even/odd chains per pred; on equal keys even (smaller idx) wins.
    int idxA, idxB;
    {
        unsigned k = bA0; int h = 0;
        if (bA1 < bA0) { k = bA1; h = 1; }
        idxA = (int)((k & 511u) << 1) | h;
        k = bB0; h = 0;
        if (bB1 < bB0) { k = bB1; h = 1; }
        idxB = (int)((k & 511u) << 1) | h;
    }

    // Gather winning targets (undo -2 prescale) and smooth-L1.
    float s;
    {
        int m2 = idxA >> 1, p = idxA & 1;
        const float* Af = (const float*)&sA[m2];
        const float* Bf = (const float*)&sB[m2];
        s = sl1(xa0, -0.5f * Af[p]) + sl1(xa1, -0.5f * Af[2 + p]) + sl1(xa2, -0.5f * Bf[p]);
        m2 = idxB >> 1; p = idxB & 1;
        Af = (const float*)&sA[m2];
        Bf = (const float*)&sB[m2];
        s += sl1(xb0, -0.5f * Af[p]) + sl1(xb1, -0.5f * Af[2 + p]) + sl1(xb2, -0.5f * Bf[p]);
    }

    // Block reductions (each thread contributes its 2 preds / 2 targets).
    float S   = blockReduceSum(s, red);
    float sx0 = blockReduceSum(xa0 + xb0, red);
    float sx1 = blockReduceSum(xa1 + xb1, red);
    float sx2 = blockReduceSum(xa2 + xb2, red);
    float st0 = blockReduceSum(ta0 + tb0, red);
    float st1 = blockReduceSum(ta1 + tb1, red);
    float st2 = blockReduceSum(ta2 + tb2, red);

    if (tid == 0) {
        g_loss_part[bt] = W[bt] * S;
        float inv = 1.0f / (float)N;
        g_lossc_part[bt] = sl1(sx0 * inv, st0 * inv)
                         + sl1(sx1 * inv, st1 * inv)
                         + sl1(sx2 * inv, st2 * inv);
        __threadfence();
        unsigned int prev = atomicAdd(&g_count, 1u);
        isLast = (prev == (unsigned int)(gridDim.x - 1)) ? 1 : 0;
    }
    __syncthreads();

    // Last CTA finalizes with warp 0 (deterministic order).
    if (isLast && tid < 32) {
        __threadfence();
        float v1 = 0.0f, v2 = 0.0f;
        for (int i = tid; i < BT; i += 32) {
            v1 += g_loss_part[i];
            v2 += g_lossc_part[i];
        }
        #pragma unroll
        for (int o = 16; o > 0; o >>= 1) {
            v1 += __shfl_down_sync(0xffffffffu, v1, o);
            v2 += __shfl_down_sync(0xffffffffu, v2, o);
        }
        if (tid == 0) {
            out[0] = v1 / (3.0f * (float)N * (float)B);
            out[1] = v2 / ((float)B * 3.0f);
            g_count = 0;   // reset for next graph replay
        }
    }
}

extern "C" void kernel_launch(void* const* d_in, const int* in_sizes, int n_in,
                              void* d_out, int out_size)
{
    const float* X = (const float*)d_in[0];   // [B,T,N,3]
    const float* T = (const float*)d_in[1];   // [B,T,N,3]
    const float* W = (const float*)d_in[2];   // [B,T]
    float* out = (float*)d_out;

    const int BT = in_sizes[2];               // 112
    const int N  = in_sizes[0] / (BT * 3);    // 1024
    const int B  = 4;

    size_t smem = (size_t)N * sizeof(float4); // 16 KB
    nn_loss_kernel<<<BT, N / 2, smem>>>(X, T, W, out, N, BT, B);
}

// round 6
// speedup vs baseline: 1.2532x; 1.0268x over previous
#include <cuda_runtime.h>
#include <math.h>
#include <float.h>

#define MAXBT 1024
__device__ float g_s  [MAXBT];
__device__ float g_px0[MAXBT];
__device__ float g_px1[MAXBT];
__device__ float g_px2[MAXBT];
__device__ float g_pt0[MAXBT];
__device__ float g_pt1[MAXBT];
__device__ float g_pt2[MAXBT];
__device__ unsigned int g_count;

typedef unsigned long long u64;

__device__ __forceinline__ u64 pk2(float lo, float hi) {
    u64 r; asm("mov.b64 %0, {%1,%2};" : "=l"(r) : "f"(lo), "f"(hi)); return r;
}
__device__ __forceinline__ void upk2(float& lo, float& hi, u64 v) {
    asm("mov.b64 {%0,%1}, %2;" : "=f"(lo), "=f"(hi) : "l"(v));
}
__device__ __forceinline__ u64 ffma2(u64 a, u64 b, u64 c) {
    u64 d; asm("fma.rn.f32x2 %0, %1, %2, %3;" : "=l"(d) : "l"(a), "l"(b), "l"(c)); return d;
}
__device__ __forceinline__ u64 addf2(u64 a, u64 b) {
    u64 d; asm("add.rn.f32x2 %0, %1, %2;" : "=l"(d) : "l"(a), "l"(b)); return d;
}

__device__ __forceinline__ float sl1(float a, float b) {
    float d = fabsf(a - b);
    return d < 1.0f ? 0.5f * d * d : d - 0.5f;
}

__device__ __forceinline__ float warpSum(float v) {
    #pragma unroll
    for (int o = 16; o > 0; o >>= 1)
        v += __shfl_down_sync(0xffffffffu, v, o);
    return v;
}

// Flat-balanced NN loss. Work unit = adjacent pred pair (2u,2u+1), always in
// one tile. grid = NSM CTAs x 512 threads; each active thread owns one unit.
// A CTA's units span <=2 tiles; both tiles' targets staged in smem banks
// (paired f32x2 layout, prescaled by -2 with squared norm).
// Argmin: packed keys, low 9 mantissa bits = m2 counter; 4 independent
// IMNMX.U32 chains (pred x parity).
__global__ __launch_bounds__(512, 1)
void nn_loss_kernel(const float* __restrict__ X,
                    const float* __restrict__ T,
                    const float* __restrict__ W,
                    float* __restrict__ out,
                    int N, int BT, int B,
                    int totalUnits, int unitsPerCta)
{
    extern __shared__ float4 smem4[];
    // bank0: smem4[0..511]=A, smem4[512..1023]=Bv ; bank1: +1024
    __shared__ int isLast;

    const int tid  = threadIdx.x;
    const int bid  = blockIdx.x;
    const int half = N >> 1;   // 512

    int uStart = bid * unitsPerCta;
    int myU = totalUnits - uStart;
    if (myU > unitsPerCta) myU = unitsPerCta;
    if (myU < 0) myU = 0;

    const int tileLo = (uStart * 2) >> 10;
    const int tileHi = (myU > 0) ? (((uStart + myU) * 2 - 1) >> 10) : tileLo;

    // ---- Stage tileLo into bank0 (thread stages targets tid, tid+half) ----
    {
        const float* Tb = T + (size_t)tileLo * N * 3;
        float4* sA = smem4;
        float4* sB = smem4 + half;
        #pragma unroll
        for (int r = 0; r < 2; ++r) {
            int i = tid + r * half;
            float t0 = Tb[i * 3 + 0], t1 = Tb[i * 3 + 1], t2 = Tb[i * 3 + 2];
            float tn = fmaf(t0, t0, fmaf(t1, t1, t2 * t2));
            int m2 = i >> 1, p = i & 1;
            float* A  = (float*)&sA[m2];
            float* Bp = (float*)&sB[m2];
            A[p] = -2.0f * t0;  A[2 + p] = -2.0f * t1;
            Bp[p] = -2.0f * t2; Bp[2 + p] = tn;
        }
    }
    // ---- Stage tileHi into bank1 if the CTA spans two tiles ----
    if (tileHi != tileLo) {
        const float* Tb = T + (size_t)tileHi * N * 3;
        float4* sA = smem4 + 2 * half;
        float4* sB = smem4 + 3 * half;
        #pragma unroll
        for (int r = 0; r < 2; ++r) {
            int i = tid + r * half;
            float t0 = Tb[i * 3 + 0], t1 = Tb[i * 3 + 1], t2 = Tb[i * 3 + 2];
            float tn = fmaf(t0, t0, fmaf(t1, t1, t2 * t2));
            int m2 = i >> 1, p = i & 1;
            float* A  = (float*)&sA[m2];
            float* Bp = (float*)&sB[m2];
            A[p] = -2.0f * t0;  A[2 + p] = -2.0f * t1;
            Bp[p] = -2.0f * t2; Bp[2 + p] = tn;
        }
    }
    __syncthreads();

    float s = 0.0f;
    float sx0 = 0.0f, sx1 = 0.0f, sx2 = 0.0f;
    float st0 = 0.0f, st1 = 0.0f, st2 = 0.0f;
    int tile = -1;

    if (tid < myU) {
        const int u = uStart + tid;
        tile = (u * 2) >> 10;

        // Two adjacent preds: global floats [6u, 6u+6), 8B-aligned.
        const float2* Xp = (const float2*)(X + (size_t)u * 6);
        float2 p0 = Xp[0], p1 = Xp[1], p2 = Xp[2];
        float xa0 = p0.x, xa1 = p0.y, xa2 = p1.x;
        float xb0 = p1.y, xb1 = p2.x, xb2 = p2.y;

        // Owned targets (same global indices as owned preds) for coord sums.
        const float2* Tp = (const float2*)(T + (size_t)u * 6);
        float2 q0 = Tp[0], q1 = Tp[1], q2 = Tp[2];
        st0 = q0.x + q1.y; st1 = q0.y + q2.x; st2 = q1.x + q2.y;
        sx0 = xa0 + xb0;   sx1 = xa1 + xb1;   sx2 = xa2 + xb2;

        float xna = fmaf(xa0, xa0, fmaf(xa1, xa1, xa2 * xa2));
        float xnb = fmaf(xb0, xb0, fmaf(xb1, xb1, xb2 * xb2));

        const float4* bank = (tile == tileLo) ? smem4 : (smem4 + 2 * half);
        const ulonglong2* pA = (const ulonglong2*)bank;
        const ulonglong2* pB = (const ulonglong2*)(bank + half);

        u64 A0 = pk2(xa0, xa0), A1 = pk2(xa1, xa1), A2 = pk2(xa2, xa2);
        u64 B0 = pk2(xb0, xb0), B1 = pk2(xb1, xb1), B2 = pk2(xb2, xb2);
        u64 NA = pk2(xna, xna), NB = pk2(xnb, xnb);

        const unsigned MASK = 0xFFFFFE00u;   // keep 14 mantissa bits, low 9 = m2
        unsigned bA0 = 0xFFFFFFFFu, bA1 = 0xFFFFFFFFu;
        unsigned bB0 = 0xFFFFFFFFu, bB1 = 0xFFFFFFFFu;

        #pragma unroll 8
        for (int m2 = 0; m2 < half; ++m2) {
            ulonglong2 a = pA[m2];
            ulonglong2 b = pB[m2];
            u64 dA = addf2(ffma2(A0, a.x, ffma2(A1, a.y, ffma2(A2, b.x, b.y))), NA);
            u64 dB = addf2(ffma2(B0, a.x, ffma2(B1, a.y, ffma2(B2, b.x, b.y))), NB);
            float dA0, dA1, dB0, dB1;
            upk2(dA0, dA1, dA);
            upk2(dB0, dB1, dB);
            unsigned mu = (unsigned)m2;
            bA0 = min(bA0, (__float_as_uint(dA0) & MASK) | mu);
            bA1 = min(bA1, (__float_as_uint(dA1) & MASK) | mu);
            bB0 = min(bB0, (__float_as_uint(dB0) & MASK) | mu);
            bB1 = min(bB1, (__float_as_uint(dB1) & MASK) | mu);
        }

        int idxA, idxB;
        {
            unsigned k = bA0; int h = 0;
            if (bA1 < bA0) { k = bA1; h = 1; }
            idxA = (int)((k & 511u) << 1) | h;
            k = bB0; h = 0;
            if (bB1 < bB0) { k = bB1; h = 1; }
            idxB = (int)((k & 511u) << 1) | h;
        }

        {
            int m2 = idxA >> 1, p = idxA & 1;
            const float* Af = (const float*)&bank[m2];
            const float* Bf = (const float*)&bank[half + m2];
            s = sl1(xa0, -0.5f * Af[p]) + sl1(xa1, -0.5f * Af[2 + p]) + sl1(xa2, -0.5f * Bf[p]);
            m2 = idxB >> 1; p = idxB & 1;
            Af = (const float*)&bank[m2];
            Bf = (const float*)&bank[half + m2];
            s += sl1(xb0, -0.5f * Af[p]) + sl1(xb1, -0.5f * Af[2 + p]) + sl1(xb2, -0.5f * Bf[p]);
        }
    }

    // ---- Per-tile accumulation: warp-uniform fast path, per-lane fallback ----
    {
        int t0 = __shfl_sync(0xffffffffu, tile, 0);
        bool uni = __all_sync(0xffffffffu, tile == t0);
        if (uni) {
            float rs  = warpSum(s);
            float r0  = warpSum(sx0), r1 = warpSum(sx1), r2 = warpSum(sx2);
            float r3  = warpSum(st0), r4 = warpSum(st1), r5 = warpSum(st2);
            if ((tid & 31) == 0 && t0 >= 0) {
                atomicAdd(&g_s[t0],   rs);
                atomicAdd(&g_px0[t0], r0); atomicAdd(&g_px1[t0], r1); atomicAdd(&g_px2[t0], r2);
                atomicAdd(&g_pt0[t0], r3); atomicAdd(&g_pt1[t0], r4); atomicAdd(&g_pt2[t0], r5);
            }
        } else if (tile >= 0) {
            atomicAdd(&g_s[tile],   s);
            atomicAdd(&g_px0[tile], sx0); atomicAdd(&g_px1[tile], sx1); atomicAdd(&g_px2[tile], sx2);
            atomicAdd(&g_pt0[tile], st0); atomicAdd(&g_pt1[tile], st1); atomicAdd(&g_pt2[tile], st2);
        }
    }

    __syncthreads();
    if (tid == 0) {
        __threadfence();
        unsigned int prev = atomicAdd(&g_count, 1u);
        isLast = (prev == (unsigned int)(gridDim.x - 1)) ? 1 : 0;
    }
    __syncthreads();

    if (isLast && tid < 32) {
        __threadfence();
        float v1 = 0.0f, v2 = 0.0f;
        float invN = 1.0f / (float)N;
        for (int i = tid; i < BT; i += 32) {
            float ss = g_s[i];
            float a0 = g_px0[i], a1 = g_px1[i], a2 = g_px2[i];
            float c0 = g_pt0[i], c1 = g_pt1[i], c2 = g_pt2[i];
            // zero for next graph replay
            g_s[i] = 0.0f;
            g_px0[i] = 0.0f; g_px1[i] = 0.0f; g_px2[i] = 0.0f;
            g_pt0[i] = 0.0f; g_pt1[i] = 0.0f; g_pt2[i] = 0.0f;
            v1 += W[i] * ss;
            v2 += sl1(a0 * invN, c0 * invN)
                + sl1(a1 * invN, c1 * invN)
                + sl1(a2 * invN, c2 * invN);
        }
        #pragma unroll
        for (int o = 16; o > 0; o >>= 1) {
            v1 += __shfl_down_sync(0xffffffffu, v1, o);
            v2 += __shfl_down_sync(0xffffffffu, v2, o);
        }
        if (tid == 0) {
            out[0] = v1 / (3.0f * (float)N * (float)B);
            out[1] = v2 / ((float)B * 3.0f);
            g_count = 0;
        }
    }
}

extern "C" void kernel_launch(void* const* d_in, const int* in_sizes, int n_in,
                              void* d_out, int out_size)
{
    const float* X = (const float*)d_in[0];   // [B,T,N,3]
    const float* T = (const float*)d_in[1];   // [B,T,N,3]
    const float* W = (const float*)d_in[2];   // [B,T]
    float* out = (float*)d_out;

    const int BT = in_sizes[2];               // 112
    const int N  = in_sizes[0] / (BT * 3);    // 1024
    const int B  = 4;

    const int NSM = 148;
    const int totalUnits = BT * (N / 2);                 // 57344
    const int unitsPerCta = (totalUnits + NSM - 1) / NSM; // 388

    size_t smem = 2 * (size_t)N * sizeof(float4);        // 32 KB (2 banks)
    nn_loss_kernel<<<NSM, 512, smem>>>(X, T, W, out, N, BT, B,
                                       totalUnits, unitsPerCta);
}

// round 7
// speedup vs baseline: 1.3219x; 1.0548x over previous
#include <cuda_runtime.h>
#include <math.h>
#include <float.h>

#define MAXBT 1024
__device__ float g_s  [MAXBT];
__device__ float g_px0[MAXBT];
__device__ float g_px1[MAXBT];
__device__ float g_px2[MAXBT];
__device__ float g_pt0[MAXBT];
__device__ float g_pt1[MAXBT];
__device__ float g_pt2[MAXBT];
__device__ unsigned int g_count;

typedef unsigned long long u64;

__device__ __forceinline__ u64 pk2(float lo, float hi) {
    u64 r; asm("mov.b64 %0, {%1,%2};" : "=l"(r) : "f"(lo), "f"(hi)); return r;
}
__device__ __forceinline__ void upk2(float& lo, float& hi, u64 v) {
    asm("mov.b64 {%0,%1}, %2;" : "=f"(lo), "=f"(hi) : "l"(v));
}
__device__ __forceinline__ u64 ffma2(u64 a, u64 b, u64 c) {
    u64 d; asm("fma.rn.f32x2 %0, %1, %2, %3;" : "=l"(d) : "l"(a), "l"(b), "l"(c)); return d;
}

__device__ __forceinline__ float sl1(float a, float b) {
    float d = fabsf(a - b);
    return d < 1.0f ? 0.5f * d * d : d - 0.5f;
}

__device__ __forceinline__ float warpSum(float v) {
    #pragma unroll
    for (int o = 16; o > 0; o >>= 1)
        v += __shfl_down_sync(0xffffffffu, v, o);
    return v;
}

// Embed low 9 bits of index into a float key's truncated mantissa.
__device__ __forceinline__ float embed(float d, unsigned idx) {
    return __uint_as_float((__float_as_uint(d) & 0xFFFFFE00u) | idx);
}

// Flat-balanced NN loss. Work unit = adjacent pred pair (2u,2u+1), always in
// one tile. grid = NSM CTAs x 512 threads; each active thread owns one unit.
// A CTA's units span <=2 tiles; both tiles' targets staged in smem banks
// (paired f32x2 layout, prescaled by -2 with squared norm).
// Argmin: key = tn - 2 x.t (signed, monotone in true dist^2), low 9 mantissa
// bits replaced by the m2 counter; 4 independent FMNMX chains (pred x parity).
// No addf2/xn bias needed -- FMNMX orders negative floats correctly.
__global__ __launch_bounds__(512, 1)
void nn_loss_kernel(const float* __restrict__ X,
                    const float* __restrict__ T,
                    const float* __restrict__ W,
                    float* __restrict__ out,
                    int N, int BT, int B,
                    int totalUnits, int unitsPerCta)
{
    extern __shared__ float4 smem4[];
    __shared__ int isLast;

    const int tid  = threadIdx.x;
    const int bid  = blockIdx.x;
    const int half = N >> 1;   // 512

    int uStart = bid * unitsPerCta;
    int myU = totalUnits - uStart;
    if (myU > unitsPerCta) myU = unitsPerCta;
    if (myU < 0) myU = 0;

    const int tileLo = (uStart * 2) >> 10;
    const int tileHi = (myU > 0) ? (((uStart + myU) * 2 - 1) >> 10) : tileLo;

    // ---- Stage tileLo into bank0 ----
    {
        const float* Tb = T + (size_t)tileLo * N * 3;
        float4* sA = smem4;
        float4* sB = smem4 + half;
        #pragma unroll
        for (int r = 0; r < 2; ++r) {
            int i = tid + r * half;
            float t0 = Tb[i * 3 + 0], t1 = Tb[i * 3 + 1], t2 = Tb[i * 3 + 2];
            float tn = fmaf(t0, t0, fmaf(t1, t1, t2 * t2));
            int m2 = i >> 1, p = i & 1;
            float* A  = (float*)&sA[m2];
            float* Bp = (float*)&sB[m2];
            A[p] = -2.0f * t0;  A[2 + p] = -2.0f * t1;
            Bp[p] = -2.0f * t2; Bp[2 + p] = tn;
        }
    }
    // ---- Stage tileHi into bank1 if the CTA spans two tiles ----
    if (tileHi != tileLo) {
        const float* Tb = T + (size_t)tileHi * N * 3;
        float4* sA = smem4 + 2 * half;
        float4* sB = smem4 + 3 * half;
        #pragma unroll
        for (int r = 0; r < 2; ++r) {
            int i = tid + r * half;
            float t0 = Tb[i * 3 + 0], t1 = Tb[i * 3 + 1], t2 = Tb[i * 3 + 2];
            float tn = fmaf(t0, t0, fmaf(t1, t1, t2 * t2));
            int m2 = i >> 1, p = i & 1;
            float* A  = (float*)&sA[m2];
            float* Bp = (float*)&sB[m2];
            A[p] = -2.0f * t0;  A[2 + p] = -2.0f * t1;
            Bp[p] = -2.0f * t2; Bp[2 + p] = tn;
        }
    }
    __syncthreads();

    float s = 0.0f;
    float sx0 = 0.0f, sx1 = 0.0f, sx2 = 0.0f;
    float st0 = 0.0f, st1 = 0.0f, st2 = 0.0f;
    int tile = -1;

    if (tid < myU) {
        const int u = uStart + tid;
        tile = (u * 2) >> 10;

        const float2* Xp = (const float2*)(X + (size_t)u * 6);
        float2 p0 = Xp[0], p1 = Xp[1], p2 = Xp[2];
        float xa0 = p0.x, xa1 = p0.y, xa2 = p1.x;
        float xb0 = p1.y, xb1 = p2.x, xb2 = p2.y;

        const float2* Tp = (const float2*)(T + (size_t)u * 6);
        float2 q0 = Tp[0], q1 = Tp[1], q2 = Tp[2];
        st0 = q0.x + q1.y; st1 = q0.y + q2.x; st2 = q1.x + q2.y;
        sx0 = xa0 + xb0;   sx1 = xa1 + xb1;   sx2 = xa2 + xb2;

        const float4* bank = (tile == tileLo) ? smem4 : (smem4 + 2 * half);
        const ulonglong2* pA = (const ulonglong2*)bank;
        const ulonglong2* pB = (const ulonglong2*)(bank + half);

        u64 A0 = pk2(xa0, xa0), A1 = pk2(xa1, xa1), A2 = pk2(xa2, xa2);
        u64 B0 = pk2(xb0, xb0), B1 = pk2(xb1, xb1), B2 = pk2(xb2, xb2);

        float bA0 = FLT_MAX, bA1 = FLT_MAX;   // pred A: even/odd chains
        float bB0 = FLT_MAX, bB1 = FLT_MAX;   // pred B

        #pragma unroll 8
        for (int m2 = 0; m2 < half; ++m2) {
            ulonglong2 a = pA[m2];   // (tx_e,tx_o),(ty_e,ty_o) prescaled by -2
            ulonglong2 b = pB[m2];   // (tz_e,tz_o),(tn_e,tn_o)
            u64 dA = ffma2(A0, a.x, ffma2(A1, a.y, ffma2(A2, b.x, b.y)));
            u64 dB = ffma2(B0, a.x, ffma2(B1, a.y, ffma2(B2, b.x, b.y)));
            float dA0, dA1, dB0, dB1;
            upk2(dA0, dA1, dA);
            upk2(dB0, dB1, dB);
            unsigned mu = (unsigned)m2;
            bA0 = fminf(bA0, embed(dA0, mu));
            bA1 = fminf(bA1, embed(dA1, mu));
            bB0 = fminf(bB0, embed(dB0, mu));
            bB1 = fminf(bB1, embed(dB1, mu));
        }

        int idxA, idxB;
        {
            float k = bA0; int h = 0;
            if (bA1 < bA0) { k = bA1; h = 1; }
            idxA = (int)((__float_as_uint(k) & 511u) << 1) | h;
            k = bB0; h = 0;
            if (bB1 < bB0) { k = bB1; h = 1; }
            idxB = (int)((__float_as_uint(k) & 511u) << 1) | h;
        }

        {
            int m2 = idxA >> 1, p = idxA & 1;
            const float* Af = (const float*)&bank[m2];
            const float* Bf = (const float*)&bank[half + m2];
            s = sl1(xa0, -0.5f * Af[p]) + sl1(xa1, -0.5f * Af[2 + p]) + sl1(xa2, -0.5f * Bf[p]);
            m2 = idxB >> 1; p = idxB & 1;
            Af = (const float*)&bank[m2];
            Bf = (const float*)&bank[half + m2];
            s += sl1(xb0, -0.5f * Af[p]) + sl1(xb1, -0.5f * Af[2 + p]) + sl1(xb2, -0.5f * Bf[p]);
        }
    }

    // ---- Per-tile accumulation: warp-uniform fast path, per-lane fallback ----
    {
        int t0 = __shfl_sync(0xffffffffu, tile, 0);
        bool uni = __all_sync(0xffffffffu, tile == t0);
        if (uni) {
            float rs  = warpSum(s);
            float r0  = warpSum(sx0), r1 = warpSum(sx1), r2 = warpSum(sx2);
            float r3  = warpSum(st0), r4 = warpSum(st1), r5 = warpSum(st2);
            if ((tid & 31) == 0 && t0 >= 0) {
                atomicAdd(&g_s[t0],   rs);
                atomicAdd(&g_px0[t0], r0); atomicAdd(&g_px1[t0], r1); atomicAdd(&g_px2[t0], r2);
                atomicAdd(&g_pt0[t0], r3); atomicAdd(&g_pt1[t0], r4); atomicAdd(&g_pt2[t0], r5);
            }
        } else if (tile >= 0) {
            atomicAdd(&g_s[tile],   s);
            atomicAdd(&g_px0[tile], sx0); atomicAdd(&g_px1[tile], sx1); atomicAdd(&g_px2[tile], sx2);
            atomicAdd(&g_pt0[tile], st0); atomicAdd(&g_pt1[tile], st1); atomicAdd(&g_pt2[tile], st2);
        }
    }

    __syncthreads();
    if (tid == 0) {
        __threadfence();
        unsigned int prev = atomicAdd(&g_count, 1u);
        isLast = (prev == (unsigned int)(gridDim.x - 1)) ? 1 : 0;
    }
    __syncthreads();

    if (isLast && tid < 32) {
        __threadfence();
        float v1 = 0.0f, v2 = 0.0f;
        float invN = 1.0f / (float)N;
        for (int i = tid; i < BT; i += 32) {
            float ss = g_s[i];
            float a0 = g_px0[i], a1 = g_px1[i], a2 = g_px2[i];
            float c0 = g_pt0[i], c1 = g_pt1[i], c2 = g_pt2[i];
            g_s[i] = 0.0f;
            g_px0[i] = 0.0f; g_px1[i] = 0.0f; g_px2[i] = 0.0f;
            g_pt0[i] = 0.0f; g_pt1[i] = 0.0f; g_pt2[i] = 0.0f;
            v1 += W[i] * ss;
            v2 += sl1(a0 * invN, c0 * invN)
                + sl1(a1 * invN, c1 * invN)
                + sl1(a2 * invN, c2 * invN);
        }
        #pragma unroll
        for (int o = 16; o > 0; o >>= 1) {
            v1 += __shfl_down_sync(0xffffffffu, v1, o);
            v2 += __shfl_down_sync(0xffffffffu, v2, o);
        }
        if (tid == 0) {
            out[0] = v1 / (3.0f * (float)N * (float)B);
            out[1] = v2 / ((float)B * 3.0f);
            g_count = 0;
        }
    }
}

extern "C" void kernel_launch(void* const* d_in, const int* in_sizes, int n_in,
                              void* d_out, int out_size)
{
    const float* X = (const float*)d_in[0];   // [B,T,N,3]
    const float* T = (const float*)d_in[1];   // [B,T,N,3]
    const float* W = (const float*)d_in[2];   // [B,T]
    float* out = (float*)d_out;

    const int BT = in_sizes[2];               // 112
    const int N  = in_sizes[0] / (BT * 3);    // 1024
    const int B  = 4;

    const int NSM = 148;
    const int totalUnits = BT * (N / 2);                 // 57344
    const int unitsPerCta = (totalUnits + NSM - 1) / NSM; // 388

    size_t smem = 2 * (size_t)N * sizeof(float4);        // 32 KB (2 banks)
    nn_loss_kernel<<<NSM, 512, smem>>>(X, T, W, out, N, BT, B,
                                       totalUnits, unitsPerCta);
}